// round 4
// baseline (speedup 1.0000x reference)
#include <cuda_runtime.h>

// ---------------- problem constants (dataset-fixed) ----------------
#define F_IN 128
#define HDIM 64
#define CDIM 2
#define NEG_SLOPE 0.2f

constexpr int MAXN = 100000;
constexpr int MAXE_TOT = 1700000;   // E (1.6M) + N self loops (100k)

// ---------------- device scratch (no allocs allowed) ----------------
__device__ float g_h1[(size_t)MAXN * HDIM];   // 25.6 MB
__device__ float g_as1[MAXN];
__device__ float g_ad1[MAXN];
__device__ float g_h2[(size_t)MAXN * CDIM];
__device__ float g_as2[MAXN];
__device__ float g_ad2[MAXN];

__device__ int g_cnt[MAXN];
__device__ int g_rowptr[MAXN + 1];
__device__ int g_cursor[MAXN];
__device__ int g_colsrc[MAXE_TOT];
__device__ int g_bsum[256];
__device__ int g_is64;

// ---------------- edge dtype probe ----------------
// If harness delivers int64 edges, every 8-byte word is in [0, N).
// If int32, the high word of most 8-byte pairs is a random index != 0.
__global__ void probe_k(const void* __restrict__ ei, int E, int N) {
    if (blockIdx.x == 0 && threadIdx.x == 0) {
        const long long* p = (const long long*)ei;
        int ok = 1;
        int lim = (E < 64) ? E : 64;
        for (int i = 0; i < lim; i++) {
            long long v = p[i];
            if (v < 0 || v >= (long long)N) { ok = 0; break; }
        }
        g_is64 = ok;
    }
}

__device__ __forceinline__ int edge_at(const void* ei, size_t idx) {
    if (g_is64) return (int)((const long long*)ei)[idx];
    return ((const int*)ei)[idx];
}

// ---------------- CSR build ----------------
__global__ void init_cnt_k(int N) {
    int i = blockIdx.x * blockDim.x + threadIdx.x;
    if (i < N) g_cnt[i] = 1;   // self loop pre-counted
}

__global__ void hist_k(const void* __restrict__ ei, int E, int N) {
    int e = blockIdx.x * blockDim.x + threadIdx.x;
    if (e >= E) return;
    int d = edge_at(ei, (size_t)E + e);
    if (d >= 0 && d < N) atomicAdd(&g_cnt[d], 1);
}

// block handles 2048 counts: reduce to block sum
__global__ void scan1_k(int N) {
    int tid = threadIdx.x, lane = tid & 31, warp = tid >> 5;
    int base = blockIdx.x * 2048 + tid * 8;
    int s = 0;
#pragma unroll
    for (int j = 0; j < 8; j++) {
        int i = base + j;
        if (i < N) s += g_cnt[i];
    }
#pragma unroll
    for (int o = 16; o; o >>= 1) s += __shfl_xor_sync(0xffffffffu, s, o);
    __shared__ int ws[8];
    if (lane == 0) ws[warp] = s;
    __syncthreads();
    if (tid == 0) {
        int t = 0;
#pragma unroll
        for (int w = 0; w < 8; w++) t += ws[w];
        g_bsum[blockIdx.x] = t;
    }
}

__global__ void scan2_k(int nb, int N) {
    if (threadIdx.x == 0) {
        int run = 0;
        for (int b = 0; b < nb; b++) { int t = g_bsum[b]; g_bsum[b] = run; run += t; }
        g_rowptr[N] = run;   // actual total (robust to clamped edges)
    }
}

__global__ void scan3_k(int N) {
    int tid = threadIdx.x, lane = tid & 31, warp = tid >> 5;
    int base = blockIdx.x * 2048 + tid * 8;
    int v[8];
    int ts = 0;
#pragma unroll
    for (int j = 0; j < 8; j++) {
        int i = base + j;
        v[j] = (i < N) ? g_cnt[i] : 0;
        ts += v[j];
    }
    int incl = ts;
#pragma unroll
    for (int o = 1; o < 32; o <<= 1) {
        int t = __shfl_up_sync(0xffffffffu, incl, o);
        if (lane >= o) incl += t;
    }
    int texcl = incl - ts;
    __shared__ int ws[8];
    if (lane == 31) ws[warp] = incl;
    __syncthreads();
    if (tid == 0) {
        int run = 0;
#pragma unroll
        for (int w = 0; w < 8; w++) { int t = ws[w]; ws[w] = run; run += t; }
    }
    __syncthreads();
    int run = g_bsum[blockIdx.x] + ws[warp] + texcl;
#pragma unroll
    for (int j = 0; j < 8; j++) {
        int i = base + j;
        if (i < N) { g_rowptr[i] = run; g_cursor[i] = run; run += v[j]; }
    }
}

__global__ void scatter_k(const void* __restrict__ ei, int E, int N) {
    int e = blockIdx.x * blockDim.x + threadIdx.x;
    if (e >= E + N) return;
    int s, d;
    if (e < E) {
        s = edge_at(ei, (size_t)e);
        d = edge_at(ei, (size_t)E + e);
        if (s < 0 || s >= N || d < 0 || d >= N) return;
    } else {
        s = d = e - E;   // self loop
    }
    int pos = atomicAdd(&g_cursor[d], 1);
    if (pos >= 0 && pos < MAXE_TOT) g_colsrc[pos] = s;
}

// ---------------- layer 1 GEMM (+ alpha projections fused) ----------------
// block: 256 threads = 8 warps, 16 rows per block (2 per warp).
// W1 (128x64 f32 = 32KB) + x tile (16x128 = 8KB) in smem.
#define GROWS 16
__global__ __launch_bounds__(256) void gemm1_k(
    const float* __restrict__ x, const float* __restrict__ W1,
    const float* __restrict__ a_src1, const float* __restrict__ a_dst1, int N) {
    __shared__ float Wsh[F_IN * HDIM];
    __shared__ float xs[GROWS * F_IN];
    int tid = threadIdx.x;
    int row0 = blockIdx.x * GROWS;
    if (row0 >= N) return;

    const float4* W4 = (const float4*)W1;
    float4* Wsh4 = (float4*)Wsh;
    for (int i = tid; i < F_IN * HDIM / 4; i += 256) Wsh4[i] = W4[i];

    int nrows = N - row0; if (nrows > GROWS) nrows = GROWS;
    const float4* x4 = (const float4*)(x + (size_t)row0 * F_IN);
    float4* xs4 = (float4*)xs;
    for (int i = tid; i < nrows * (F_IN / 4); i += 256) xs4[i] = x4[i];
    __syncthreads();

    int lane = tid & 31, warp = tid >> 5;
    float2 asv = ((const float2*)a_src1)[lane];
    float2 adv = ((const float2*)a_dst1)[lane];
    const float2* Wsh2 = (const float2*)Wsh;

    int r0 = warp * 2;
    if (r0 >= nrows) return;
    const float* xa = xs + r0 * F_IN;
    const float* xb = xs + ((r0 + 1 < GROWS) ? (r0 + 1) : r0) * F_IN;
    float a0 = 0.f, a1 = 0.f, b0 = 0.f, b1 = 0.f;
#pragma unroll 8
    for (int k = 0; k < F_IN; k++) {
        float2 wv = Wsh2[k * 32 + lane];
        float xva = xa[k];
        float xvb = xb[k];
        a0 = fmaf(xva, wv.x, a0);
        a1 = fmaf(xva, wv.y, a1);
        b0 = fmaf(xvb, wv.x, b0);
        b1 = fmaf(xvb, wv.y, b1);
    }
#pragma unroll
    for (int rr = 0; rr < 2; rr++) {
        int row = row0 + r0 + rr;
        if (r0 + rr >= nrows) break;
        float c0 = rr ? b0 : a0;
        float c1 = rr ? b1 : a1;
        ((float2*)(g_h1 + (size_t)row * HDIM))[lane] = make_float2(c0, c1);
        float aps = c0 * asv.x + c1 * asv.y;
        float apd = c0 * adv.x + c1 * adv.y;
#pragma unroll
        for (int o = 16; o; o >>= 1) {
            aps += __shfl_xor_sync(0xffffffffu, aps, o);
            apd += __shfl_xor_sync(0xffffffffu, apd, o);
        }
        if (lane == 0) { g_as1[row] = aps; g_ad1[row] = apd; }
    }
}

// ---------------- layer 1 aggregation + relu + layer 2 GEMM + alpha2 ----------------
// one warp per dst node, lanes own 2 features each; edges iterated serially.
__global__ __launch_bounds__(256) void agg1_k(
    const float* __restrict__ b1, const float* __restrict__ W2,
    const float* __restrict__ a_src2, const float* __restrict__ a_dst2, int N) {
    int gw = (int)((blockIdx.x * blockDim.x + threadIdx.x) >> 5);
    int lane = threadIdx.x & 31;
    if (gw >= N) return;
    int d = gw;
    int beg = g_rowptr[d], end = g_rowptr[d + 1];
    float ad = g_ad1[d];
    float accx = 0.f, accy = 0.f, den = 0.f;
    for (int e = beg; e < end; e++) {
        int s = g_colsrc[e];
        float ev = g_as1[s] + ad;
        ev = ev > 0.f ? ev : NEG_SLOPE * ev;
        float p = __expf(ev);
        float2 hv = ((const float2*)(g_h1 + (size_t)s * HDIM))[lane];
        accx = fmaf(p, hv.x, accx);
        accy = fmaf(p, hv.y, accy);
        den += p;
    }
    float inv = 1.0f / (den + 1e-16f);
    float2 bv = ((const float2*)b1)[lane];
    float h0 = accx * inv + bv.x; h0 = h0 > 0.f ? h0 : 0.f;
    float h1 = accy * inv + bv.y; h1 = h1 > 0.f ? h1 : 0.f;
    // fused layer-2 GEMM: [64] @ [64,2]
    float4 w4 = ((const float4*)W2)[lane];  // W2[2l][0..1], W2[2l+1][0..1]
    float c0 = h0 * w4.x + h1 * w4.z;
    float c1 = h0 * w4.y + h1 * w4.w;
#pragma unroll
    for (int o = 16; o; o >>= 1) {
        c0 += __shfl_xor_sync(0xffffffffu, c0, o);
        c1 += __shfl_xor_sync(0xffffffffu, c1, o);
    }
    if (lane == 0) {
        ((float2*)g_h2)[d] = make_float2(c0, c1);
        g_as2[d] = c0 * a_src2[0] + c1 * a_src2[1];
        g_ad2[d] = c0 * a_dst2[0] + c1 * a_dst2[1];
    }
}

// ---------------- layer 2 aggregation ----------------
// one warp per dst node, lanes stride over edges, 3-value butterfly reduce.
__global__ __launch_bounds__(256) void agg2_k(const float* __restrict__ b2,
                                              float* __restrict__ out, int N) {
    int gw = (int)((blockIdx.x * blockDim.x + threadIdx.x) >> 5);
    int lane = threadIdx.x & 31;
    if (gw >= N) return;
    int d = gw;
    int beg = g_rowptr[d], end = g_rowptr[d + 1];
    float ad = g_ad2[d];
    float a0 = 0.f, a1 = 0.f, den = 0.f;
    for (int e = beg + lane; e < end; e += 32) {
        int s = g_colsrc[e];
        float ev = g_as2[s] + ad;
        ev = ev > 0.f ? ev : NEG_SLOPE * ev;
        float p = __expf(ev);
        float2 hv = ((const float2*)g_h2)[s];
        a0 = fmaf(p, hv.x, a0);
        a1 = fmaf(p, hv.y, a1);
        den += p;
    }
#pragma unroll
    for (int o = 16; o; o >>= 1) {
        a0 += __shfl_xor_sync(0xffffffffu, a0, o);
        a1 += __shfl_xor_sync(0xffffffffu, a1, o);
        den += __shfl_xor_sync(0xffffffffu, den, o);
    }
    if (lane == 0) {
        float inv = 1.0f / (den + 1e-16f);
        ((float2*)out)[d] = make_float2(a0 * inv + b2[0], a1 * inv + b2[1]);
    }
}

// ---------------- launch ----------------
extern "C" void kernel_launch(void* const* d_in, const int* in_sizes, int n_in,
                              void* d_out, int out_size) {
    const float* x        = (const float*)d_in[0];
    const void*  ei       = (const void*)d_in[1];   // int32 or int64, probed on device
    const float* W1       = (const float*)d_in[2];
    const float* a_src1   = (const float*)d_in[3];
    const float* a_dst1   = (const float*)d_in[4];
    const float* b1       = (const float*)d_in[5];
    const float* W2       = (const float*)d_in[6];
    const float* a_src2   = (const float*)d_in[7];
    const float* a_dst2   = (const float*)d_in[8];
    const float* b2       = (const float*)d_in[9];

    int N = in_sizes[0] / F_IN;
    int E = in_sizes[1] / 2;

    // edge dtype probe
    probe_k<<<1, 32>>>(ei, E, N);

    // CSR build (counting sort by dst, self loops appended)
    init_cnt_k<<<(N + 255) / 256, 256>>>(N);
    hist_k<<<(E + 255) / 256, 256>>>(ei, E, N);
    int nb = (N + 2047) / 2048;
    scan1_k<<<nb, 256>>>(N);
    scan2_k<<<1, 32>>>(nb, N);
    scan3_k<<<nb, 256>>>(N);
    scatter_k<<<(E + N + 255) / 256, 256>>>(ei, E, N);

    // layer 1 GEMM + alpha projections
    gemm1_k<<<(N + GROWS - 1) / GROWS, 256>>>(x, W1, a_src1, a_dst1, N);
    // layer 1 softmax-aggregate + bias + relu + layer 2 GEMM + alpha2
    agg1_k<<<(N + 7) / 8, 256>>>(b1, W2, a_src2, a_dst2, N);
    // layer 2 softmax-aggregate + bias -> output [N, 2]
    agg2_k<<<(N + 7) / 8, 256>>>(b2, (float*)d_out, N);
}

// round 5
// speedup vs baseline: 1.2771x; 1.2771x over previous
#include <cuda_runtime.h>
#include <cuda_fp16.h>

// ---------------- problem constants (dataset-fixed) ----------------
#define F_IN 128
#define HDIM 64
#define NEG_SLOPE 0.2f

constexpr int MAXN = 100000;
constexpr int MAXE_TOT = 1700000;   // E (1.6M) + N self loops (100k)

// ---------------- device scratch ----------------
__device__ __half2 g_h1h[(size_t)MAXN * (HDIM / 2)];   // 12.8 MB, fp16 features
__device__ float g_as1[MAXN];
__device__ float g_ad1[MAXN];
__device__ float g_h2[(size_t)MAXN * 2];
__device__ float g_as2[MAXN];
__device__ float g_ad2[MAXN];

__device__ int g_cnt[MAXN];
__device__ int g_rowptr[MAXN + 1];
__device__ int g_cursor[MAXN];
__device__ int g_colsrc[MAXE_TOT];
__device__ int g_bsum[256];
__device__ int g_is64;

// ---------------- f32x2 helpers (Blackwell packed fp32) ----------------
__device__ __forceinline__ unsigned long long f32x2_fma(
    unsigned long long a, unsigned long long b, unsigned long long c) {
    unsigned long long d;
    asm("fma.rn.f32x2 %0, %1, %2, %3;" : "=l"(d) : "l"(a), "l"(b), "l"(c));
    return d;
}
__device__ __forceinline__ unsigned long long f32x2_bcast(float x) {
    unsigned long long d;
    unsigned int u = __float_as_uint(x);
    asm("mov.b64 %0, {%1, %1};" : "=l"(d) : "r"(u));
    return d;
}

// ---------------- setup: cnt init + parallel dtype probe ----------------
__global__ void setup_k(const void* __restrict__ ei, int E, int N) {
    int i = blockIdx.x * blockDim.x + threadIdx.x;
    if (i < N) g_cnt[i] = 1;   // self loop pre-counted
    if (blockIdx.x == 0) {
        // int64 edges => every 8-byte word in [0,N). int32 => high words random.
        __shared__ int bad[2];
        int tid = threadIdx.x;
        if (tid < 2) bad[tid] = 0;
        __syncthreads();
        int lim = (E < 64) ? E : 64;
        if (tid < 64) {
            int notok = 0;
            if (tid < lim) {
                long long v = ((const long long*)ei)[tid];
                if (v < 0 || v >= (long long)N) notok = 1;
            }
#pragma unroll
            for (int o = 16; o; o >>= 1) notok |= __shfl_xor_sync(0xffffffffu, notok, o);
            if ((tid & 31) == 0) bad[tid >> 5] = notok;
        }
        __syncthreads();
        if (tid == 0) g_is64 = !(bad[0] | bad[1]);
    }
}

__device__ __forceinline__ int edge_at(const void* ei, size_t idx) {
    if (g_is64) return (int)((const long long*)ei)[idx];
    return ((const int*)ei)[idx];
}

// ---------------- CSR build ----------------
__global__ void hist_k(const void* __restrict__ ei, int E, int N) {
    int e = blockIdx.x * blockDim.x + threadIdx.x;
    if (e >= E) return;
    int d = edge_at(ei, (size_t)E + e);
    if (d >= 0 && d < N) atomicAdd(&g_cnt[d], 1);
}

// block handles 2048 counts: reduce to block sum
__global__ void scan1_k(int N) {
    int tid = threadIdx.x, lane = tid & 31, warp = tid >> 5;
    int base = blockIdx.x * 2048 + tid * 8;
    int s = 0;
#pragma unroll
    for (int j = 0; j < 8; j++) {
        int i = base + j;
        if (i < N) s += g_cnt[i];
    }
#pragma unroll
    for (int o = 16; o; o >>= 1) s += __shfl_xor_sync(0xffffffffu, s, o);
    __shared__ int ws[8];
    if (lane == 0) ws[warp] = s;
    __syncthreads();
    if (tid == 0) {
        int t = 0;
#pragma unroll
        for (int w = 0; w < 8; w++) t += ws[w];
        g_bsum[blockIdx.x] = t;
    }
}

// per-block scan; block base computed inline from g_bsum (nb <= 64)
__global__ void scan3_k(int N, int nb) {
    int tid = threadIdx.x, lane = tid & 31, warp = tid >> 5;
    __shared__ int pre[4];   // [warp][{prefix, total}] for 2 warps
    if (tid < 64) {
        int v = 0, vt = 0;
        if (tid < nb) {
            int t = g_bsum[tid];
            vt = t;
            if (tid < blockIdx.x) v = t;
        }
#pragma unroll
        for (int o = 16; o; o >>= 1) {
            v  += __shfl_xor_sync(0xffffffffu, v,  o);
            vt += __shfl_xor_sync(0xffffffffu, vt, o);
        }
        if (lane == 0) { pre[warp * 2] = v; pre[warp * 2 + 1] = vt; }
    }
    __syncthreads();
    int base_blk = pre[0] + pre[2];
    if (blockIdx.x == gridDim.x - 1 && tid == 0) g_rowptr[N] = pre[1] + pre[3];

    int base = blockIdx.x * 2048 + tid * 8;
    int v[8];
    int ts = 0;
#pragma unroll
    for (int j = 0; j < 8; j++) {
        int i = base + j;
        v[j] = (i < N) ? g_cnt[i] : 0;
        ts += v[j];
    }
    int incl = ts;
#pragma unroll
    for (int o = 1; o < 32; o <<= 1) {
        int t = __shfl_up_sync(0xffffffffu, incl, o);
        if (lane >= o) incl += t;
    }
    int texcl = incl - ts;
    __shared__ int ws[8];
    if (lane == 31) ws[warp] = incl;
    __syncthreads();
    if (tid == 0) {
        int run = 0;
#pragma unroll
        for (int w = 0; w < 8; w++) { int t = ws[w]; ws[w] = run; run += t; }
    }
    __syncthreads();
    int run = base_blk + ws[warp] + texcl;
#pragma unroll
    for (int j = 0; j < 8; j++) {
        int i = base + j;
        if (i < N) { g_rowptr[i] = run; g_cursor[i] = run; run += v[j]; }
    }
}

__global__ void scatter_k(const void* __restrict__ ei, int E, int N) {
    int e = blockIdx.x * blockDim.x + threadIdx.x;
    if (e >= E + N) return;
    int s, d;
    if (e < E) {
        s = edge_at(ei, (size_t)e);
        d = edge_at(ei, (size_t)E + e);
        if (s < 0 || s >= N || d < 0 || d >= N) return;
    } else {
        s = d = e - E;   // self loop
    }
    int pos = atomicAdd(&g_cursor[d], 1);
    if (pos >= 0 && pos < MAXE_TOT) g_colsrc[pos] = s;
}

// ---------------- layer 1 GEMM via packed fma.f32x2 ----------------
// 256 threads: lane = colpair (64 cols = 32 pairs), warp (8) owns 8 rows.
// 64 rows/block. Dynamic smem: Wsh [128][64] 32KB + xs [64][128] 32KB.
#define G1ROWS 64
__global__ __launch_bounds__(256) void gemm1_k(
    const float* __restrict__ x, const float* __restrict__ W1,
    const float* __restrict__ a_src1, const float* __restrict__ a_dst1, int N) {
    extern __shared__ float smem[];
    float* Wsh = smem;                 // 8192 floats
    float* xs  = smem + F_IN * HDIM;   // 8192 floats
    int tid = threadIdx.x;
    int row0 = blockIdx.x * G1ROWS;
    if (row0 >= N) return;

    const float4* W4 = (const float4*)W1;
    float4* Wsh4 = (float4*)Wsh;
#pragma unroll
    for (int i = tid; i < F_IN * HDIM / 4; i += 256) Wsh4[i] = W4[i];

    int nrows = N - row0; if (nrows > G1ROWS) nrows = G1ROWS;
    const float4* x4 = (const float4*)(x + (size_t)row0 * F_IN);
    float4* xs4 = (float4*)xs;
    for (int i = tid; i < nrows * (F_IN / 4); i += 256) xs4[i] = x4[i];
    __syncthreads();

    int lane = tid & 31, warp = tid >> 5;
    int r0 = warp * 8;
    const unsigned long long* Wsh8 = (const unsigned long long*)Wsh;

    unsigned long long acc[8];
#pragma unroll
    for (int r = 0; r < 8; r++) acc[r] = 0ull;

    for (int k0 = 0; k0 < F_IN; k0 += 4) {
        float4 xv[8];
#pragma unroll
        for (int r = 0; r < 8; r++)
            xv[r] = *(const float4*)&xs[(r0 + r) * F_IN + k0];
#pragma unroll
        for (int kk = 0; kk < 4; kk++) {
            unsigned long long wp = Wsh8[(k0 + kk) * 32 + lane];
#pragma unroll
            for (int r = 0; r < 8; r++) {
                float xk = (kk == 0) ? xv[r].x : (kk == 1) ? xv[r].y
                          : (kk == 2) ? xv[r].z : xv[r].w;
                acc[r] = f32x2_fma(f32x2_bcast(xk), wp, acc[r]);
            }
        }
    }

    float2 asv = ((const float2*)a_src1)[lane];
    float2 adv = ((const float2*)a_dst1)[lane];
#pragma unroll
    for (int r = 0; r < 8; r++) {
        int lr = r0 + r;
        if (lr >= nrows) break;
        int row = row0 + lr;
        float c0 = __uint_as_float((unsigned int)acc[r]);
        float c1 = __uint_as_float((unsigned int)(acc[r] >> 32));
        g_h1h[(size_t)row * 32 + lane] = __floats2half2_rn(c0, c1);
        float aps = c0 * asv.x + c1 * asv.y;
        float apd = c0 * adv.x + c1 * adv.y;
#pragma unroll
        for (int o = 16; o; o >>= 1) {
            aps += __shfl_xor_sync(0xffffffffu, aps, o);
            apd += __shfl_xor_sync(0xffffffffu, apd, o);
        }
        if (lane == 0) { g_as1[row] = aps; g_ad1[row] = apd; }
    }
}

// ---------------- layer 1 aggregation + relu + layer 2 GEMM + alpha2 ----------------
// warp per dst. Lanes batch-load 32 edges (colsrc + alpha), then shfl-broadcast
// into independent 128B h1 gathers: no dependent-load chain, MLP ~32.
__global__ __launch_bounds__(256) void agg1_k(
    const float* __restrict__ b1, const float* __restrict__ W2,
    const float* __restrict__ a_src2, const float* __restrict__ a_dst2, int N) {
    int gw = (int)((blockIdx.x * blockDim.x + threadIdx.x) >> 5);
    int lane = threadIdx.x & 31;
    if (gw >= N) return;
    int d = gw;
    int beg = g_rowptr[d], end = g_rowptr[d + 1];
    float ad = g_ad1[d];
    float accx = 0.f, accy = 0.f, denl = 0.f;
    for (int base = beg; base < end; base += 32) {
        int m = end - base; if (m > 32) m = 32;
        int s_l = 0; float p_l = 0.f;
        if (lane < m) {
            s_l = g_colsrc[base + lane];
            float ev = g_as1[s_l] + ad;
            ev = ev > 0.f ? ev : NEG_SLOPE * ev;
            p_l = __expf(ev);
        }
        denl += p_l;
#pragma unroll 4
        for (int j = 0; j < m; j++) {
            int s  = __shfl_sync(0xffffffffu, s_l, j);
            float p = __shfl_sync(0xffffffffu, p_l, j);
            __half2 hv = g_h1h[(size_t)s * 32 + lane];
            float2 f = __half22float2(hv);
            accx = fmaf(p, f.x, accx);
            accy = fmaf(p, f.y, accy);
        }
    }
    float den = denl;
#pragma unroll
    for (int o = 16; o; o >>= 1) den += __shfl_xor_sync(0xffffffffu, den, o);
    float inv = 1.0f / (den + 1e-16f);
    float2 bv = ((const float2*)b1)[lane];
    float h0 = accx * inv + bv.x; h0 = h0 > 0.f ? h0 : 0.f;
    float h1 = accy * inv + bv.y; h1 = h1 > 0.f ? h1 : 0.f;
    // fused layer-2 GEMM: [64] @ [64,2]
    float4 w4 = ((const float4*)W2)[lane];  // W2[2l][0..1], W2[2l+1][0..1]
    float c0 = h0 * w4.x + h1 * w4.z;
    float c1 = h0 * w4.y + h1 * w4.w;
#pragma unroll
    for (int o = 16; o; o >>= 1) {
        c0 += __shfl_xor_sync(0xffffffffu, c0, o);
        c1 += __shfl_xor_sync(0xffffffffu, c1, o);
    }
    if (lane == 0) {
        ((float2*)g_h2)[d] = make_float2(c0, c1);
        g_as2[d] = c0 * a_src2[0] + c1 * a_src2[1];
        g_ad2[d] = c0 * a_dst2[0] + c1 * a_dst2[1];
    }
}

// ---------------- layer 2 aggregation ----------------
__global__ __launch_bounds__(256) void agg2_k(const float* __restrict__ b2,
                                              float* __restrict__ out, int N) {
    int gw = (int)((blockIdx.x * blockDim.x + threadIdx.x) >> 5);
    int lane = threadIdx.x & 31;
    if (gw >= N) return;
    int d = gw;
    int beg = g_rowptr[d], end = g_rowptr[d + 1];
    float ad = g_ad2[d];
    float a0 = 0.f, a1 = 0.f, den = 0.f;
    for (int e = beg + lane; e < end; e += 32) {
        int s = g_colsrc[e];
        float ev = g_as2[s] + ad;
        ev = ev > 0.f ? ev : NEG_SLOPE * ev;
        float p = __expf(ev);
        float2 hv = ((const float2*)g_h2)[s];
        a0 = fmaf(p, hv.x, a0);
        a1 = fmaf(p, hv.y, a1);
        den += p;
    }
#pragma unroll
    for (int o = 16; o; o >>= 1) {
        a0 += __shfl_xor_sync(0xffffffffu, a0, o);
        a1 += __shfl_xor_sync(0xffffffffu, a1, o);
        den += __shfl_xor_sync(0xffffffffu, den, o);
    }
    if (lane == 0) {
        float inv = 1.0f / (den + 1e-16f);
        ((float2*)out)[d] = make_float2(a0 * inv + b2[0], a1 * inv + b2[1]);
    }
}

// ---------------- launch ----------------
extern "C" void kernel_launch(void* const* d_in, const int* in_sizes, int n_in,
                              void* d_out, int out_size) {
    const float* x        = (const float*)d_in[0];
    const void*  ei       = (const void*)d_in[1];   // int32 or int64, probed on device
    const float* W1       = (const float*)d_in[2];
    const float* a_src1   = (const float*)d_in[3];
    const float* a_dst1   = (const float*)d_in[4];
    const float* b1       = (const float*)d_in[5];
    const float* W2       = (const float*)d_in[6];
    const float* a_src2   = (const float*)d_in[7];
    const float* a_dst2   = (const float*)d_in[8];
    const float* b2       = (const float*)d_in[9];

    int N = in_sizes[0] / F_IN;
    int E = in_sizes[1] / 2;

    static int smem_set = 0;
    if (!smem_set) {
        cudaFuncSetAttribute(gemm1_k, cudaFuncAttributeMaxDynamicSharedMemorySize,
                             2 * F_IN * HDIM * (int)sizeof(float));
        smem_set = 1;
    }

    // CSR build (counting sort by dst, self loops appended)
    setup_k<<<(N + 255) / 256, 256>>>(ei, E, N);
    hist_k<<<(E + 255) / 256, 256>>>(ei, E, N);
    int nb = (N + 2047) / 2048;   // 49 for N=100k (inline prefix assumes <= 64)
    scan1_k<<<nb, 256>>>(N);
    scan3_k<<<nb, 256>>>(N, nb);
    scatter_k<<<(E + N + 255) / 256, 256>>>(ei, E, N);

    // layer 1 GEMM (f32x2) + alpha projections, h1 stored fp16
    gemm1_k<<<(N + G1ROWS - 1) / G1ROWS, 256, 2 * F_IN * HDIM * sizeof(float)>>>(
        x, W1, a_src1, a_dst1, N);
    // layer 1 softmax-aggregate + bias + relu + layer 2 GEMM + alpha2
    agg1_k<<<(N + 7) / 8, 256>>>(b1, W2, a_src2, a_dst2, N);
    // layer 2 softmax-aggregate + bias -> output [N, 2]
    agg2_k<<<(N + 7) / 8, 256>>>(b2, (float*)d_out, N);
}

// round 6
// speedup vs baseline: 1.3267x; 1.0389x over previous
#include <cuda_runtime.h>
#include <cuda_fp16.h>

// ---------------- problem constants (dataset-fixed) ----------------
#define F_IN 128
#define HDIM 64
#define NEG_SLOPE 0.2f

constexpr int MAXN = 100000;
constexpr int MAXE_TOT = 1700000;   // E (1.6M) + N self loops (100k)

// ---------------- device scratch ----------------
__device__ __half2 g_h1h[(size_t)MAXN * (HDIM / 2)];   // 12.8 MB, fp16 features
__device__ float g_as1[MAXN];
__device__ float g_ad1[MAXN];
__device__ float4 g_pack2[MAXN];          // {h2.x, h2.y, as2, ad2}

__device__ int g_cnt[MAXN];               // zero-init; re-zeroed by scan3 each replay
__device__ int g_rowptr[MAXN + 1];
__device__ int g_cursor[MAXN];
__device__ int g_colsrc[MAXE_TOT];
__device__ int g_bsum[256];
__device__ int g_is64;

// ---------------- f32x2 helpers (Blackwell packed fp32) ----------------
__device__ __forceinline__ unsigned long long f32x2_fma(
    unsigned long long a, unsigned long long b, unsigned long long c) {
    unsigned long long d;
    asm("fma.rn.f32x2 %0, %1, %2, %3;" : "=l"(d) : "l"(a), "l"(b), "l"(c));
    return d;
}
__device__ __forceinline__ unsigned long long f32x2_bcast(float x) {
    unsigned long long d;
    unsigned int u = __float_as_uint(x);
    asm("mov.b64 %0, {%1, %1};" : "=l"(d) : "r"(u));
    return d;
}

// ---------------- edge dtype probe (1 block) ----------------
__global__ void probe_k(const void* __restrict__ ei, int E, int N) {
    __shared__ int bad[2];
    int tid = threadIdx.x;
    if (tid < 2) bad[tid] = 0;
    __syncthreads();
    int lim = (E < 64) ? E : 64;
    if (tid < 64) {
        int notok = 0;
        if (tid < lim) {
            long long v = ((const long long*)ei)[tid];
            if (v < 0 || v >= (long long)N) notok = 1;
        }
#pragma unroll
        for (int o = 16; o; o >>= 1) notok |= __shfl_xor_sync(0xffffffffu, notok, o);
        if ((tid & 31) == 0) bad[tid >> 5] = notok;
    }
    __syncthreads();
    if (tid == 0) g_is64 = !(bad[0] | bad[1]);
}

__device__ __forceinline__ int edge_at(const void* ei, size_t idx) {
    if (g_is64) return (int)((const long long*)ei)[idx];
    return ((const int*)ei)[idx];
}

// ---------------- CSR build ----------------
__global__ void hist_k(const void* __restrict__ ei, int E, int N) {
    int e = blockIdx.x * blockDim.x + threadIdx.x;
    if (e >= E) return;
    int d = edge_at(ei, (size_t)E + e);
    if (d >= 0 && d < N) atomicAdd(&g_cnt[d], 1);
}

// block handles 2048 counts: reduce to block sum (self-loop +1 folded in)
__global__ void scan1_k(int N) {
    int tid = threadIdx.x, lane = tid & 31, warp = tid >> 5;
    int base = blockIdx.x * 2048 + tid * 8;
    int s = 0;
#pragma unroll
    for (int j = 0; j < 8; j++) {
        int i = base + j;
        if (i < N) s += g_cnt[i] + 1;
    }
#pragma unroll
    for (int o = 16; o; o >>= 1) s += __shfl_xor_sync(0xffffffffu, s, o);
    __shared__ int ws[8];
    if (lane == 0) ws[warp] = s;
    __syncthreads();
    if (tid == 0) {
        int t = 0;
#pragma unroll
        for (int w = 0; w < 8; w++) t += ws[w];
        g_bsum[blockIdx.x] = t;
    }
}

// per-block scan; block base computed inline from g_bsum (nb <= 64).
// Also re-zeros g_cnt so the next graph replay starts clean.
__global__ void scan3_k(int N, int nb) {
    int tid = threadIdx.x, lane = tid & 31, warp = tid >> 5;
    __shared__ int pre[4];   // [warp][{prefix, total}] for 2 warps
    if (tid < 64) {
        int v = 0, vt = 0;
        if (tid < nb) {
            int t = g_bsum[tid];
            vt = t;
            if (tid < blockIdx.x) v = t;
        }
#pragma unroll
        for (int o = 16; o; o >>= 1) {
            v  += __shfl_xor_sync(0xffffffffu, v,  o);
            vt += __shfl_xor_sync(0xffffffffu, vt, o);
        }
        if (lane == 0) { pre[warp * 2] = v; pre[warp * 2 + 1] = vt; }
    }
    __syncthreads();
    int base_blk = pre[0] + pre[2];
    if (blockIdx.x == gridDim.x - 1 && tid == 0) g_rowptr[N] = pre[1] + pre[3];

    int base = blockIdx.x * 2048 + tid * 8;
    int v[8];
    int ts = 0;
#pragma unroll
    for (int j = 0; j < 8; j++) {
        int i = base + j;
        v[j] = (i < N) ? (g_cnt[i] + 1) : 0;
        ts += v[j];
    }
    int incl = ts;
#pragma unroll
    for (int o = 1; o < 32; o <<= 1) {
        int t = __shfl_up_sync(0xffffffffu, incl, o);
        if (lane >= o) incl += t;
    }
    int texcl = incl - ts;
    __shared__ int ws[8];
    if (lane == 31) ws[warp] = incl;
    __syncthreads();
    if (tid == 0) {
        int run = 0;
#pragma unroll
        for (int w = 0; w < 8; w++) { int t = ws[w]; ws[w] = run; run += t; }
    }
    __syncthreads();
    int run = base_blk + ws[warp] + texcl;
#pragma unroll
    for (int j = 0; j < 8; j++) {
        int i = base + j;
        if (i < N) {
            g_rowptr[i] = run; g_cursor[i] = run; run += v[j];
            g_cnt[i] = 0;   // reset for next replay
        }
    }
}

__global__ void scatter_k(const void* __restrict__ ei, int E, int N) {
    int e = blockIdx.x * blockDim.x + threadIdx.x;
    if (e >= E + N) return;
    int s, d;
    if (e < E) {
        s = edge_at(ei, (size_t)e);
        d = edge_at(ei, (size_t)E + e);
        if (s < 0 || s >= N || d < 0 || d >= N) return;
    } else {
        s = d = e - E;   // self loop
    }
    int pos = atomicAdd(&g_cursor[d], 1);
    if (pos >= 0 && pos < MAXE_TOT) g_colsrc[pos] = s;
}

// ---------------- layer 1 GEMM via packed fma.f32x2 ----------------
// 256 threads: lane = colpair (64 cols = 32 pairs), warp (8) owns 8 rows.
// 64 rows/block. Dynamic smem: Wsh [128][64] 32KB + xs [64][128] 32KB.
#define G1ROWS 64
__global__ __launch_bounds__(256) void gemm1_k(
    const float* __restrict__ x, const float* __restrict__ W1,
    const float* __restrict__ a_src1, const float* __restrict__ a_dst1, int N) {
    extern __shared__ float smem[];
    float* Wsh = smem;                 // 8192 floats
    float* xs  = smem + F_IN * HDIM;   // 8192 floats
    int tid = threadIdx.x;
    int row0 = blockIdx.x * G1ROWS;
    if (row0 >= N) return;

    const float4* W4 = (const float4*)W1;
    float4* Wsh4 = (float4*)Wsh;
#pragma unroll
    for (int i = tid; i < F_IN * HDIM / 4; i += 256) Wsh4[i] = W4[i];

    int nrows = N - row0; if (nrows > G1ROWS) nrows = G1ROWS;
    const float4* x4 = (const float4*)(x + (size_t)row0 * F_IN);
    float4* xs4 = (float4*)xs;
    for (int i = tid; i < nrows * (F_IN / 4); i += 256) xs4[i] = x4[i];
    __syncthreads();

    int lane = tid & 31, warp = tid >> 5;
    int r0 = warp * 8;
    const unsigned long long* Wsh8 = (const unsigned long long*)Wsh;

    unsigned long long acc[8];
#pragma unroll
    for (int r = 0; r < 8; r++) acc[r] = 0ull;

    for (int k0 = 0; k0 < F_IN; k0 += 4) {
        float4 xv[8];
#pragma unroll
        for (int r = 0; r < 8; r++)
            xv[r] = *(const float4*)&xs[(r0 + r) * F_IN + k0];
#pragma unroll
        for (int kk = 0; kk < 4; kk++) {
            unsigned long long wp = Wsh8[(k0 + kk) * 32 + lane];
#pragma unroll
            for (int r = 0; r < 8; r++) {
                float xk = (kk == 0) ? xv[r].x : (kk == 1) ? xv[r].y
                          : (kk == 2) ? xv[r].z : xv[r].w;
                acc[r] = f32x2_fma(f32x2_bcast(xk), wp, acc[r]);
            }
        }
    }

    float2 asv = ((const float2*)a_src1)[lane];
    float2 adv = ((const float2*)a_dst1)[lane];
#pragma unroll
    for (int r = 0; r < 8; r++) {
        int lr = r0 + r;
        if (lr >= nrows) break;
        int row = row0 + lr;
        float c0 = __uint_as_float((unsigned int)acc[r]);
        float c1 = __uint_as_float((unsigned int)(acc[r] >> 32));
        g_h1h[(size_t)row * 32 + lane] = __floats2half2_rn(c0, c1);
        float aps = c0 * asv.x + c1 * asv.y;
        float apd = c0 * adv.x + c1 * adv.y;
#pragma unroll
        for (int o = 16; o; o >>= 1) {
            aps += __shfl_xor_sync(0xffffffffu, aps, o);
            apd += __shfl_xor_sync(0xffffffffu, apd, o);
        }
        if (lane == 0) { g_as1[row] = aps; g_ad1[row] = apd; }
    }
}

// ---------------- layer 1 aggregation + relu + layer 2 GEMM + alpha2 ----------------
// warp per dst. Lanes batch-load 32 edges (colsrc + alpha), then shfl-broadcast
// into independent 128B h1 gathers: no dependent-load chain, MLP ~32.
__global__ __launch_bounds__(256) void agg1_k(
    const float* __restrict__ b1, const float* __restrict__ W2,
    const float* __restrict__ a_src2, const float* __restrict__ a_dst2, int N) {
    int gw = (int)((blockIdx.x * blockDim.x + threadIdx.x) >> 5);
    int lane = threadIdx.x & 31;
    if (gw >= N) return;
    int d = gw;
    int beg = g_rowptr[d], end = g_rowptr[d + 1];
    float ad = g_ad1[d];
    float accx = 0.f, accy = 0.f, denl = 0.f;
    for (int base = beg; base < end; base += 32) {
        int m = end - base; if (m > 32) m = 32;
        int s_l = 0; float p_l = 0.f;
        if (lane < m) {
            s_l = g_colsrc[base + lane];
            float ev = g_as1[s_l] + ad;
            ev = ev > 0.f ? ev : NEG_SLOPE * ev;
            p_l = __expf(ev);
        }
        denl += p_l;
#pragma unroll 4
        for (int j = 0; j < m; j++) {
            int s  = __shfl_sync(0xffffffffu, s_l, j);
            float p = __shfl_sync(0xffffffffu, p_l, j);
            __half2 hv = g_h1h[(size_t)s * 32 + lane];
            float2 f = __half22float2(hv);
            accx = fmaf(p, f.x, accx);
            accy = fmaf(p, f.y, accy);
        }
    }
    float den = denl;
#pragma unroll
    for (int o = 16; o; o >>= 1) den += __shfl_xor_sync(0xffffffffu, den, o);
    float inv = 1.0f / (den + 1e-16f);
    float2 bv = ((const float2*)b1)[lane];
    float h0 = accx * inv + bv.x; h0 = h0 > 0.f ? h0 : 0.f;
    float h1 = accy * inv + bv.y; h1 = h1 > 0.f ? h1 : 0.f;
    // fused layer-2 GEMM: [64] @ [64,2]
    float4 w4 = ((const float4*)W2)[lane];  // W2[2l][0..1], W2[2l+1][0..1]
    float c0 = h0 * w4.x + h1 * w4.z;
    float c1 = h0 * w4.y + h1 * w4.w;
#pragma unroll
    for (int o = 16; o; o >>= 1) {
        c0 += __shfl_xor_sync(0xffffffffu, c0, o);
        c1 += __shfl_xor_sync(0xffffffffu, c1, o);
    }
    if (lane == 0) {
        g_pack2[d] = make_float4(c0, c1,
                                 c0 * a_src2[0] + c1 * a_src2[1],
                                 c0 * a_dst2[0] + c1 * a_dst2[1]);
    }
}

// ---------------- layer 2 aggregation ----------------
// one random 16B load per edge: {h2.x, h2.y, as2, ad2} packed.
__global__ __launch_bounds__(256) void agg2_k(const float* __restrict__ b2,
                                              float* __restrict__ out, int N) {
    int gw = (int)((blockIdx.x * blockDim.x + threadIdx.x) >> 5);
    int lane = threadIdx.x & 31;
    if (gw >= N) return;
    int d = gw;
    int beg = g_rowptr[d], end = g_rowptr[d + 1];
    float ad = g_pack2[d].w;
    float a0 = 0.f, a1 = 0.f, den = 0.f;
    for (int e = beg + lane; e < end; e += 32) {
        int s = g_colsrc[e];
        float4 pv = g_pack2[s];
        float ev = pv.z + ad;
        ev = ev > 0.f ? ev : NEG_SLOPE * ev;
        float p = __expf(ev);
        a0 = fmaf(p, pv.x, a0);
        a1 = fmaf(p, pv.y, a1);
        den += p;
    }
#pragma unroll
    for (int o = 16; o; o >>= 1) {
        a0 += __shfl_xor_sync(0xffffffffu, a0, o);
        a1 += __shfl_xor_sync(0xffffffffu, a1, o);
        den += __shfl_xor_sync(0xffffffffu, den, o);
    }
    if (lane == 0) {
        float inv = 1.0f / (den + 1e-16f);
        ((float2*)out)[d] = make_float2(a0 * inv + b2[0], a1 * inv + b2[1]);
    }
}

// ---------------- launch ----------------
extern "C" void kernel_launch(void* const* d_in, const int* in_sizes, int n_in,
                              void* d_out, int out_size) {
    const float* x        = (const float*)d_in[0];
    const void*  ei       = (const void*)d_in[1];   // int32 or int64, probed on device
    const float* W1       = (const float*)d_in[2];
    const float* a_src1   = (const float*)d_in[3];
    const float* a_dst1   = (const float*)d_in[4];
    const float* b1       = (const float*)d_in[5];
    const float* W2       = (const float*)d_in[6];
    const float* a_src2   = (const float*)d_in[7];
    const float* a_dst2   = (const float*)d_in[8];
    const float* b2       = (const float*)d_in[9];

    int N = in_sizes[0] / F_IN;
    int E = in_sizes[1] / 2;

    static int inited = 0;
    static int have_stream = 0;
    static cudaStream_t s2;
    static cudaEvent_t evFork, evJoin;
    if (!inited) {
        cudaFuncSetAttribute(gemm1_k, cudaFuncAttributeMaxDynamicSharedMemorySize,
                             2 * F_IN * HDIM * (int)sizeof(float));
        if (cudaStreamCreateWithFlags(&s2, cudaStreamNonBlocking) == cudaSuccess &&
            cudaEventCreateWithFlags(&evFork, cudaEventDisableTiming) == cudaSuccess &&
            cudaEventCreateWithFlags(&evJoin, cudaEventDisableTiming) == cudaSuccess) {
            have_stream = 1;
        }
        inited = 1;
    }

    size_t g1smem = 2 * F_IN * HDIM * sizeof(float);
    int g1grid = (N + G1ROWS - 1) / G1ROWS;

    if (have_stream) {
        // fork: gemm1 on side stream, CSR build on main stream, join before agg1
        cudaEventRecord(evFork, 0);
        cudaStreamWaitEvent(s2, evFork, 0);
        gemm1_k<<<g1grid, 256, g1smem, s2>>>(x, W1, a_src1, a_dst1, N);
        cudaEventRecord(evJoin, s2);
    } else {
        gemm1_k<<<g1grid, 256, g1smem>>>(x, W1, a_src1, a_dst1, N);
    }

    // CSR build (counting sort by dst, self loops folded into scans)
    probe_k<<<1, 64>>>(ei, E, N);
    hist_k<<<(E + 255) / 256, 256>>>(ei, E, N);
    int nb = (N + 2047) / 2048;   // 49 for N=100k (inline prefix assumes <= 64)
    scan1_k<<<nb, 256>>>(N);
    scan3_k<<<nb, 256>>>(N, nb);
    scatter_k<<<(E + N + 255) / 256, 256>>>(ei, E, N);

    if (have_stream) cudaStreamWaitEvent(0, evJoin, 0);

    // layer 1 softmax-aggregate + bias + relu + layer 2 GEMM + alpha2
    agg1_k<<<(N + 7) / 8, 256>>>(b1, W2, a_src2, a_dst2, N);
    // layer 2 softmax-aggregate + bias -> output [N, 2]
    agg2_k<<<(N + 7) / 8, 256>>>(b2, (float*)d_out, N);
}